// round 11
// baseline (speedup 1.0000x reference)
#include <cuda_runtime.h>

// ---------------------------------------------------------------------------
// GCN 2-layer forward. CSR aggregation + column-split f32x2 GEMM1 pipeline.
//   h1 = x @ W1          [N,128]  — two 64-col halves (FFMA2, v1-style tiles)
//   hid = relu(A @ h1 + b1)       — two halves; half A overlaps gemm1 half B
//   h2 = hid @ W2        [N,16]
//   out = log_softmax(A @ h2 + b2)
// edge_index is int32 (JAX x64-disabled truncates the requested int64).
// CSR build forked onto a side stream, overlapped with GEMM1 half A.
// ---------------------------------------------------------------------------

#define NMAX 50000
#define EMAX 800000
typedef unsigned long long ull;

__device__ int   g_indeg [NMAX];
__device__ int   g_cursor[NMAX];
__device__ int   g_rowptr[NMAX + 1];
__device__ int   g_scan  [NMAX];
__device__ int   g_bsum  [256];
__device__ int   g_boff  [256];
__device__ float g_dinv  [NMAX];
__device__ __align__(16) ull   g_emeta[EMAX];        // hi: norm bits, lo: src
__device__ __align__(16) float g_h1   [NMAX * 128];
__device__ __align__(16) float g_hid  [NMAX * 128];
__device__ __align__(16) float g_h2   [NMAX * 16];

// ---------------- f32x2 helpers --------------------------------------------

__device__ __forceinline__ void fma2(ull& acc, ull a, ull b) {
    asm("fma.rn.f32x2 %0, %1, %2, %0;" : "+l"(acc) : "l"(a), "l"(b));
}
__device__ __forceinline__ ull dup2(float w) {
    ull d; unsigned u = __float_as_uint(w);
    asm("mov.b64 %0, {%1, %1};" : "=l"(d) : "r"(u));
    return d;
}
__device__ __forceinline__ float f2lo(ull v) { return __uint_as_float((unsigned)v); }
__device__ __forceinline__ float f2hi(ull v) { return __uint_as_float((unsigned)(v >> 32)); }

// ---------------- CSR build ------------------------------------------------

__global__ void k_init(int n) {
    int i = blockIdx.x * blockDim.x + threadIdx.x;
    if (i < n) { g_indeg[i] = 0; g_cursor[i] = 0; }
}

__global__ void k_deg_count(const int* __restrict__ dst, int E) {
    int e = blockIdx.x * blockDim.x + threadIdx.x;
    if (e < E) atomicAdd(&g_indeg[dst[e]], 1);
}

__global__ void k_scan1(int n) {
    __shared__ int wsum[8];
    int t = threadIdx.x, i = blockIdx.x * 256 + t;
    int lane = t & 31, w = t >> 5;
    int x = (i < n) ? g_indeg[i] : 0;
#pragma unroll
    for (int o = 1; o < 32; o <<= 1) {
        int y = __shfl_up_sync(0xffffffffu, x, o);
        if (lane >= o) x += y;
    }
    if (lane == 31) wsum[w] = x;
    __syncthreads();
    if (w == 0) {
        int s = (lane < 8) ? wsum[lane] : 0;
#pragma unroll
        for (int o = 1; o < 8; o <<= 1) {
            int y = __shfl_up_sync(0xffffffffu, s, o);
            if (lane >= o) s += y;
        }
        if (lane < 8) wsum[lane] = s;
    }
    __syncthreads();
    if (w > 0) x += wsum[w - 1];
    if (i < n) g_scan[i] = x;
    if (t == 255) g_bsum[blockIdx.x] = x;
}

__global__ void k_scan2(int nb) {
    __shared__ int wsum[8];
    int t = threadIdx.x;
    int lane = t & 31, w = t >> 5;
    int v = (t < nb) ? g_bsum[t] : 0;
    int x = v;
#pragma unroll
    for (int o = 1; o < 32; o <<= 1) {
        int y = __shfl_up_sync(0xffffffffu, x, o);
        if (lane >= o) x += y;
    }
    if (lane == 31) wsum[w] = x;
    __syncthreads();
    if (w == 0) {
        int s = (lane < 8) ? wsum[lane] : 0;
#pragma unroll
        for (int o = 1; o < 8; o <<= 1) {
            int y = __shfl_up_sync(0xffffffffu, s, o);
            if (lane >= o) s += y;
        }
        if (lane < 8) wsum[lane] = s;
    }
    __syncthreads();
    if (w > 0) x += wsum[w - 1];
    g_boff[t] = x - v;   // exclusive
}

__global__ void k_scan3(int n) {     // rowptr + dinv
    int i = blockIdx.x * blockDim.x + threadIdx.x;
    if (i >= n) return;
    int deg = g_indeg[i];
    int off = g_boff[i >> 8];
    g_rowptr[i] = g_scan[i] - deg + off;
    if (i == n - 1) g_rowptr[n] = g_scan[i] + off;
    g_dinv[i] = rsqrtf((float)(deg + 1));
}

__global__ void k_fill(const int* __restrict__ src, const int* __restrict__ dst, int E) {
    int e = blockIdx.x * blockDim.x + threadIdx.x;
    if (e >= E) return;
    int s = src[e], d = dst[e];
    int pos = g_rowptr[d] + atomicAdd(&g_cursor[d], 1);
    float nm = g_dinv[s] * g_dinv[d];
    g_emeta[pos] = ((ull)__float_as_uint(nm) << 32) | (unsigned)s;
}

// ---------------- GEMM1 half: h1[:, coff:coff+64] = x @ W1[:, coff:+64] ----
// 64 rows x 64 cols per block, K-chunks of 64, 32KB smem, v1-style layout.
// Per thread: 4 rows (2 f32x2 row-pairs) x 4 cols.

__global__ void __launch_bounds__(256) k_gemm1h(const float* __restrict__ X,
                                                const float* __restrict__ W,
                                                int n, int coff) {
    __shared__ float XsT[64][64];   // [k][row]
    __shared__ float Ws [64][64];   // [k][col]
    const int tid  = threadIdx.x;
    const int tcol = tid & 15;      // cols 4*tcol .. +3
    const int trow = tid >> 4;      // rows 4*trow .. +3
    const int row0 = blockIdx.x * 64;
    const int rbase = trow << 2;

    ull acc[2][4];
#pragma unroll
    for (int rp = 0; rp < 2; rp++)
#pragma unroll
        for (int c = 0; c < 4; c++) acc[rp][c] = 0ull;

    for (int k0 = 0; k0 < 256; k0 += 64) {
        // stage X transposed (conflict-free STS; same as proven v1)
#pragma unroll
        for (int i = tid; i < 1024; i += 256) {
            int r = i & 63, c = (i >> 6) << 2;
            int gr = row0 + r;
            float4 v = make_float4(0.f, 0.f, 0.f, 0.f);
            if (gr < n) v = *(const float4*)(X + (size_t)gr * 256 + k0 + c);
            XsT[c + 0][r] = v.x;
            XsT[c + 1][r] = v.y;
            XsT[c + 2][r] = v.z;
            XsT[c + 3][r] = v.w;
        }
        // stage W half (coalesced LDG)
#pragma unroll
        for (int i = tid; i < 1024; i += 256) {
            int r = i >> 4, c = (i & 15) << 2;
            *(float4*)&Ws[r][c] = *(const float4*)(W + (size_t)(k0 + r) * 128 + coff + c);
        }
        __syncthreads();

#pragma unroll 8
        for (int kk = 0; kk < 64; kk++) {
            float4 wq = *(float4*)&Ws[kk][tcol << 2];   // 16 addrs x 16B: 2-phase
            ull wd0 = dup2(wq.x), wd1 = dup2(wq.y), wd2 = dup2(wq.z), wd3 = dup2(wq.w);
            ull x0 = *(const ull*)&XsT[kk][rbase + 0];  // 2-addr broadcast
            ull x1 = *(const ull*)&XsT[kk][rbase + 2];
            fma2(acc[0][0], x0, wd0); fma2(acc[0][1], x0, wd1);
            fma2(acc[0][2], x0, wd2); fma2(acc[0][3], x0, wd3);
            fma2(acc[1][0], x1, wd0); fma2(acc[1][1], x1, wd1);
            fma2(acc[1][2], x1, wd2); fma2(acc[1][3], x1, wd3);
        }
        __syncthreads();
    }

#pragma unroll
    for (int rp = 0; rp < 2; rp++) {
        int r0 = row0 + rbase + (rp << 1);
        if (r0 < n)
            *(float4*)(g_h1 + (size_t)r0 * 128 + coff + (tcol << 2)) =
                make_float4(f2lo(acc[rp][0]), f2lo(acc[rp][1]),
                            f2lo(acc[rp][2]), f2lo(acc[rp][3]));
        if (r0 + 1 < n)
            *(float4*)(g_h1 + (size_t)(r0 + 1) * 128 + coff + (tcol << 2)) =
                make_float4(f2hi(acc[rp][0]), f2hi(acc[rp][1]),
                            f2hi(acc[rp][2]), f2hi(acc[rp][3]));
    }
}

// ---------------- gather1 half (warp per node, float2/lane) ----------------

__global__ void __launch_bounds__(256) k_gather1h(const float* __restrict__ b1,
                                                  int n, int coff) {
    int node = (blockIdx.x * 256 + threadIdx.x) >> 5;
    int lane = threadIdx.x & 31;
    if (node >= n) return;
    int c = coff + (lane << 1);

    float di  = g_dinv[node];
    float di2 = di * di;
    float2 h  = *(const float2*)(g_h1 + (size_t)node * 128 + c);
    float2 a;
    a.x = di2 * h.x; a.y = di2 * h.y;

    int beg = g_rowptr[node], end = g_rowptr[node + 1];
    if (beg < end) {
        ull m0 = g_emeta[beg];
        float2 v0 = *(const float2*)(g_h1 + (size_t)(unsigned)m0 * 128 + c);
        for (int e = beg + 1; e < end; e++) {
            ull m1 = g_emeta[e];                                        // prefetch
            float2 v1 = *(const float2*)(g_h1 + (size_t)(unsigned)m1 * 128 + c);
            float nm = __uint_as_float((unsigned)(m0 >> 32));
            a.x += nm * v0.x; a.y += nm * v0.y;
            m0 = m1; v0 = v1;
        }
        float nm = __uint_as_float((unsigned)(m0 >> 32));
        a.x += nm * v0.x; a.y += nm * v0.y;
    }
    float2 b = *(const float2*)(b1 + c);
    float2 o;
    o.x = fmaxf(a.x + b.x, 0.f);
    o.y = fmaxf(a.y + b.y, 0.f);
    *(float2*)(g_hid + (size_t)node * 128 + c) = o;
}

// ---------------- GEMM2: h2 = hid @ W2  (K=128, 16 cols) -------------------

__global__ void __launch_bounds__(256) k_gemm2(const float* __restrict__ W2, int n) {
    __shared__ float Xs[64][132];
    __shared__ float Ws[128 * 16];
    const int tid  = threadIdx.x;
    const int row0 = blockIdx.x * 64;

#pragma unroll
    for (int i = tid; i < 512; i += 256)
        ((float4*)Ws)[i] = ((const float4*)W2)[i];

#pragma unroll
    for (int i = tid; i < 64 * 32; i += 256) {
        int r = i >> 5, c = (i & 31) << 2;
        int gr = row0 + r;
        float4 v = make_float4(0.f, 0.f, 0.f, 0.f);
        if (gr < n) v = *(const float4*)(g_hid + (size_t)gr * 128 + c);
        *(float4*)&Xs[r][c] = v;
    }
    __syncthreads();

    const int tcol = tid & 3;
    const int trow = tid >> 2;
    float acc[4] = {0.f, 0.f, 0.f, 0.f};
#pragma unroll 8
    for (int k = 0; k < 128; k++) {
        float  xv = Xs[trow][k];
        float4 wv = *(float4*)&Ws[k * 16 + (tcol << 2)];
        acc[0] += xv * wv.x;
        acc[1] += xv * wv.y;
        acc[2] += xv * wv.z;
        acc[3] += xv * wv.w;
    }
    int gr = row0 + trow;
    if (gr < n)
        *(float4*)(g_h2 + (size_t)gr * 16 + (tcol << 2)) =
            make_float4(acc[0], acc[1], acc[2], acc[3]);
}

// ---------------- gather layer 2 + log_softmax (4 lanes per node) ----------

__global__ void __launch_bounds__(256) k_gather2(const float* __restrict__ b2,
                                                 float* __restrict__ out, int n) {
    int g    = blockIdx.x * 256 + threadIdx.x;
    int node = g >> 2, q = g & 3;
    if (node >= n) return;
    int c = q << 2;

    float di  = g_dinv[node];
    float di2 = di * di;
    float4 h  = *(const float4*)(g_h2 + (size_t)node * 16 + c);
    float4 a;
    a.x = di2 * h.x; a.y = di2 * h.y; a.z = di2 * h.z; a.w = di2 * h.w;

    int beg = g_rowptr[node], end = g_rowptr[node + 1];
    if (beg < end) {
        ull m0 = g_emeta[beg];
        float4 v0 = *(const float4*)(g_h2 + (size_t)(unsigned)m0 * 16 + c);
        for (int e = beg + 1; e < end; e++) {
            ull m1 = g_emeta[e];
            float4 v1 = *(const float4*)(g_h2 + (size_t)(unsigned)m1 * 16 + c);
            float nm = __uint_as_float((unsigned)(m0 >> 32));
            a.x += nm * v0.x; a.y += nm * v0.y; a.z += nm * v0.z; a.w += nm * v0.w;
            m0 = m1; v0 = v1;
        }
        float nm = __uint_as_float((unsigned)(m0 >> 32));
        a.x += nm * v0.x; a.y += nm * v0.y; a.z += nm * v0.z; a.w += nm * v0.w;
    }
    float4 b = *(const float4*)(b2 + c);
    a.x += b.x; a.y += b.y; a.z += b.z; a.w += b.w;

    float m4 = fmaxf(fmaxf(a.x, a.y), fmaxf(a.z, a.w));
    m4 = fmaxf(m4, __shfl_xor_sync(0xffffffffu, m4, 1, 4));
    m4 = fmaxf(m4, __shfl_xor_sync(0xffffffffu, m4, 2, 4));
    float s4 = expf(a.x - m4) + expf(a.y - m4) + expf(a.z - m4) + expf(a.w - m4);
    s4 += __shfl_xor_sync(0xffffffffu, s4, 1, 4);
    s4 += __shfl_xor_sync(0xffffffffu, s4, 2, 4);
    float lse = m4 + logf(s4);

    float4 o;
    o.x = a.x - lse; o.y = a.y - lse; o.z = a.z - lse; o.w = a.w - lse;
    *(float4*)(out + (size_t)node * 16 + c) = o;
}

// ---------------------------------------------------------------------------

extern "C" void kernel_launch(void* const* d_in, const int* in_sizes, int n_in,
                              void* d_out, int out_size) {
    const float* x  = (const float*)d_in[0];
    const int*   ei = (const int*)d_in[1];          // int32 (JAX truncation)
    const float* W1 = (const float*)d_in[2];
    const float* b1 = (const float*)d_in[3];
    const float* W2 = (const float*)d_in[4];
    const float* b2 = (const float*)d_in[5];
    float*       out = (float*)d_out;

    const int n = in_sizes[0] / 256;
    const int E = in_sizes[1] / 2;
    const int* src = ei;
    const int* dst = ei + E;
    const int nb = (n + 255) / 256;

    const int T = 256;
    dim3 b(T);

    static cudaStream_t sCsr = nullptr, sOvl = nullptr;
    static cudaEvent_t  eFork = nullptr, eJoin = nullptr, eA = nullptr, eG0 = nullptr;
    if (!sCsr) {
        cudaStreamCreateWithFlags(&sCsr, cudaStreamNonBlocking);
        cudaStreamCreateWithFlags(&sOvl, cudaStreamNonBlocking);
        cudaEventCreateWithFlags(&eFork, cudaEventDisableTiming);
        cudaEventCreateWithFlags(&eJoin, cudaEventDisableTiming);
        cudaEventCreateWithFlags(&eA,    cudaEventDisableTiming);
        cudaEventCreateWithFlags(&eG0,   cudaEventDisableTiming);
    }

    // fork: CSR build on side stream
    cudaEventRecord(eFork, 0);
    cudaStreamWaitEvent(sCsr, eFork, 0);

    k_init     <<<(n + T - 1) / T, b, 0, sCsr>>>(n);
    k_deg_count<<<(E + T - 1) / T, b, 0, sCsr>>>(dst, E);
    k_scan1    <<<nb, b, 0, sCsr>>>(n);

    // main: GEMM1 half A (cols 0..63)
    k_gemm1h<<<(n + 63) / 64, b>>>(x, W1, n, 0);
    cudaEventRecord(eA, 0);

    k_scan2    <<<1, b, 0, sCsr>>>(nb);
    k_scan3    <<<nb, b, 0, sCsr>>>(n);
    k_fill     <<<(E + T - 1) / T, b, 0, sCsr>>>(src, dst, E);
    cudaEventRecord(eJoin, sCsr);

    // main: GEMM1 half B (cols 64..127), overlapped with gather1 half A
    k_gemm1h<<<(n + 63) / 64, b>>>(x, W1, n, 64);

    // overlap stream: gather1 half A (needs h1 half A + CSR)
    cudaStreamWaitEvent(sOvl, eA, 0);
    cudaStreamWaitEvent(sOvl, eJoin, 0);
    k_gather1h<<<(n * 32 + T - 1) / T, b, 0, sOvl>>>(b1, n, 0);
    cudaEventRecord(eG0, sOvl);

    // main: gather1 half B (needs h1 half B [stream order] + CSR)
    cudaStreamWaitEvent(0, eJoin, 0);
    k_gather1h<<<(n * 32 + T - 1) / T, b>>>(b1, n, 64);

    // join half A, then the tail chain
    cudaStreamWaitEvent(0, eG0, 0);
    k_gemm2  <<<(n + 63) / 64, b>>>(W2, n);
    k_gather2<<<(n * 4 + T - 1) / T, b>>>(b2, out, n);
}

// round 12
// speedup vs baseline: 1.1973x; 1.1973x over previous
#include <cuda_runtime.h>

// ---------------------------------------------------------------------------
// GCN 2-layer forward. CSR aggregation + f32x2 GEMM1 v3 (X-dup packing).
//   h1 = x @ W1                    [N,128]  (FFMA2, col-pair packing)
//   hid = relu(A @ h1 + b1)        (registers/smem only)
//   h2 = hid @ W2                  [N,16]   (fused into gather1)
//   out = log_softmax(A @ h2 + b2) [N,16]
// edge_index is int32 (JAX x64-disabled truncates the requested int64).
// CSR build forked onto a side stream, overlapped with GEMM1.
// ---------------------------------------------------------------------------

#define NMAX 50000
#define EMAX 800000
typedef unsigned long long ull;

__device__ int   g_indeg [NMAX];
__device__ int   g_cursor[NMAX];
__device__ int   g_rowptr[NMAX + 1];
__device__ int   g_scan  [NMAX];
__device__ int   g_bsum  [256];
__device__ int   g_boff  [256];
__device__ float g_dinv  [NMAX];
__device__ __align__(16) ull   g_emeta[EMAX];        // hi: norm bits, lo: src
__device__ __align__(16) float g_h1   [NMAX * 128];
__device__ __align__(16) float g_h2   [NMAX * 16];

// ---------------- f32x2 helpers --------------------------------------------

__device__ __forceinline__ void fma2(ull& acc, ull a, ull b) {
    asm("fma.rn.f32x2 %0, %1, %2, %0;" : "+l"(acc) : "l"(a), "l"(b));
}
__device__ __forceinline__ ull dup2(float w) {
    ull d; unsigned u = __float_as_uint(w);
    asm("mov.b64 %0, {%1, %1};" : "=l"(d) : "r"(u));
    return d;
}
__device__ __forceinline__ float f2lo(ull v) { return __uint_as_float((unsigned)v); }
__device__ __forceinline__ float f2hi(ull v) { return __uint_as_float((unsigned)(v >> 32)); }

// ---------------- CSR build ------------------------------------------------

__global__ void k_init(int n) {
    int i = blockIdx.x * blockDim.x + threadIdx.x;
    if (i < n) { g_indeg[i] = 0; g_cursor[i] = 0; }
}

__global__ void k_deg_count(const int* __restrict__ dst, int E) {
    int e = blockIdx.x * blockDim.x + threadIdx.x;
    if (e < E) atomicAdd(&g_indeg[dst[e]], 1);
}

__global__ void k_scan1(int n) {
    __shared__ int wsum[8];
    int t = threadIdx.x, i = blockIdx.x * 256 + t;
    int lane = t & 31, w = t >> 5;
    int x = (i < n) ? g_indeg[i] : 0;
#pragma unroll
    for (int o = 1; o < 32; o <<= 1) {
        int y = __shfl_up_sync(0xffffffffu, x, o);
        if (lane >= o) x += y;
    }
    if (lane == 31) wsum[w] = x;
    __syncthreads();
    if (w == 0) {
        int s = (lane < 8) ? wsum[lane] : 0;
#pragma unroll
        for (int o = 1; o < 8; o <<= 1) {
            int y = __shfl_up_sync(0xffffffffu, s, o);
            if (lane >= o) s += y;
        }
        if (lane < 8) wsum[lane] = s;
    }
    __syncthreads();
    if (w > 0) x += wsum[w - 1];
    if (i < n) g_scan[i] = x;
    if (t == 255) g_bsum[blockIdx.x] = x;
}

__global__ void k_scan2(int nb) {
    __shared__ int wsum[8];
    int t = threadIdx.x;
    int lane = t & 31, w = t >> 5;
    int v = (t < nb) ? g_bsum[t] : 0;
    int x = v;
#pragma unroll
    for (int o = 1; o < 32; o <<= 1) {
        int y = __shfl_up_sync(0xffffffffu, x, o);
        if (lane >= o) x += y;
    }
    if (lane == 31) wsum[w] = x;
    __syncthreads();
    if (w == 0) {
        int s = (lane < 8) ? wsum[lane] : 0;
#pragma unroll
        for (int o = 1; o < 8; o <<= 1) {
            int y = __shfl_up_sync(0xffffffffu, s, o);
            if (lane >= o) s += y;
        }
        if (lane < 8) wsum[lane] = s;
    }
    __syncthreads();
    if (w > 0) x += wsum[w - 1];
    g_boff[t] = x - v;   // exclusive
}

__global__ void k_scan3(int n) {     // rowptr + dinv
    int i = blockIdx.x * blockDim.x + threadIdx.x;
    if (i >= n) return;
    int deg = g_indeg[i];
    int off = g_boff[i >> 8];
    g_rowptr[i] = g_scan[i] - deg + off;
    if (i == n - 1) g_rowptr[n] = g_scan[i] + off;
    g_dinv[i] = rsqrtf((float)(deg + 1));
}

__global__ void k_fill(const int* __restrict__ src, const int* __restrict__ dst, int E) {
    int e = blockIdx.x * blockDim.x + threadIdx.x;
    if (e >= E) return;
    int s = src[e], d = dst[e];
    int pos = g_rowptr[d] + atomicAdd(&g_cursor[d], 1);
    float nm = g_dinv[s] * g_dinv[d];
    g_emeta[pos] = ((ull)__float_as_uint(nm) << 32) | (unsigned)s;
}

// ---------------- GEMM1 v3: h1 = x @ W1  (K=256, 128 cols) -----------------
// 128x128 tile, 256 threads, 8 rows x 8 cols per thread, K-chunks of 16.
// X stored as DUPLICATED f32x2 (x,x) per row in smem (dup paid at staging);
// W stored natural — inner-loop W reads are plain packed LDS.128, no dup.
// FFMA2 pairs COLUMNS: acc(2c,2c+1) += (x,x)*(w_2c,w_2c+1).
// Per warp-kk: 4 bcast LDS.128 (X) + 2x2-phase LDS.128 (W) = 8 crossbar
// phases per 32-FFMA2 window -> crossbar parity; issue-bound at 1.19x floor.

__global__ void __launch_bounds__(256, 2) k_gemm1(const float* __restrict__ X,
                                                  const float* __restrict__ W,
                                                  int n) {
    __shared__ ull   XsD[16][130];   // [kk][row] = (x,x); pad 130 keeps 16B align
    __shared__ float Wn [16][128];   // [kk][col] natural
    const int tid = threadIdx.x;
    const int cg  = tid & 15;        // cols 8*cg .. +7  (colpairs 4cg..4cg+3)
    const int rg  = tid >> 4;        // rows 8*rg .. +7
    const int row0 = blockIdx.x * 128;
    const int rbase = rg << 3;

    ull acc[8][4];
#pragma unroll
    for (int r = 0; r < 8; r++)
#pragma unroll
        for (int c = 0; c < 4; c++) acc[r][c] = 0ull;

    for (int ch = 0; ch < 16; ch++) {
        const int k0 = ch << 4;
        // ---- stage X: 128 rows x 16 k, dup-packed ----
#pragma unroll
        for (int i = tid; i < 512; i += 256) {
            int r = i >> 2, f4 = i & 3;
            int gr = row0 + r;
            float4 v = make_float4(0.f, 0.f, 0.f, 0.f);
            if (gr < n) v = *(const float4*)(X + (size_t)gr * 256 + k0 + (f4 << 2));
            XsD[(f4 << 2) + 0][r] = dup2(v.x);
            XsD[(f4 << 2) + 1][r] = dup2(v.y);
            XsD[(f4 << 2) + 2][r] = dup2(v.z);
            XsD[(f4 << 2) + 3][r] = dup2(v.w);
        }
        // ---- stage W natural: 16 k x 128 cols ----
#pragma unroll
        for (int i = tid; i < 512; i += 256) {
            int kk = i >> 5, c0 = (i & 31) << 2;
            *(float4*)&Wn[kk][c0] = *(const float4*)(W + (size_t)(k0 + kk) * 128 + c0);
        }
        __syncthreads();

#pragma unroll
        for (int kk = 0; kk < 16; kk++) {
            // W: 2 packed LDS.128 -> 4 natural col-pairs
            ull w01 = *(const ull*)&Wn[kk][cg << 3];
            ull w23 = *(const ull*)&Wn[kk][(cg << 3) + 2];
            ull w45 = *(const ull*)&Wn[kk][(cg << 3) + 4];
            ull w67 = *(const ull*)&Wn[kk][(cg << 3) + 6];
            // X: 4 broadcast LDS.128 -> 8 row dups
#pragma unroll
            for (int j = 0; j < 4; j++) {
                ull xa = XsD[kk][rbase + 2 * j];
                ull xb = XsD[kk][rbase + 2 * j + 1];
                fma2(acc[2 * j][0], xa, w01);
                fma2(acc[2 * j][1], xa, w23);
                fma2(acc[2 * j][2], xa, w45);
                fma2(acc[2 * j][3], xa, w67);
                fma2(acc[2 * j + 1][0], xb, w01);
                fma2(acc[2 * j + 1][1], xb, w23);
                fma2(acc[2 * j + 1][2], xb, w45);
                fma2(acc[2 * j + 1][3], xb, w67);
            }
        }
        __syncthreads();
    }

    // ---- epilogue: acc[r][cp] = cols (8cg+2cp, +2cp+1) of row row0+rbase+r --
#pragma unroll
    for (int r = 0; r < 8; r++) {
        int gr = row0 + rbase + r;
        if (gr < n) {
            *(float4*)(g_h1 + (size_t)gr * 128 + (cg << 3)) =
                make_float4(f2lo(acc[r][0]), f2hi(acc[r][0]),
                            f2lo(acc[r][1]), f2hi(acc[r][1]));
            *(float4*)(g_h1 + (size_t)gr * 128 + (cg << 3) + 4) =
                make_float4(f2lo(acc[r][2]), f2hi(acc[r][2]),
                            f2lo(acc[r][3]), f2hi(acc[r][3]));
        }
    }
}

// ---------------- fused gather1 + GEMM2 (warp per node) --------------------

__global__ void __launch_bounds__(256) k_gather1_gemm2(const float* __restrict__ b1,
                                                       const float* __restrict__ W2,
                                                       int n) {
    __shared__ float W2s[16][132];        // W2s[j][k] = W2[k][j] (transposed, padded)
    __shared__ float hidS[8][128];        // per-warp hid row
    const int tid  = threadIdx.x;
    const int w    = tid >> 5;
    const int lane = tid & 31;

#pragma unroll
    for (int i = tid; i < 2048; i += 256) {
        int k = i >> 4, j = i & 15;
        W2s[j][k] = W2[k * 16 + j];
    }
    __syncthreads();

    int node = blockIdx.x * 8 + w;
    if (node >= n) return;
    int c = lane << 2;

    float di  = g_dinv[node];
    float di2 = di * di;
    float4 h  = *(const float4*)(g_h1 + (size_t)node * 128 + c);
    float4 a;
    a.x = di2 * h.x; a.y = di2 * h.y; a.z = di2 * h.z; a.w = di2 * h.w;

    int beg = g_rowptr[node], end = g_rowptr[node + 1];
    if (beg < end) {
        ull m0 = g_emeta[beg];
        float4 v0 = *(const float4*)(g_h1 + (size_t)(unsigned)m0 * 128 + c);
        for (int e = beg + 1; e < end; e++) {
            ull m1 = g_emeta[e];
            float4 v1 = *(const float4*)(g_h1 + (size_t)(unsigned)m1 * 128 + c);
            float nm = __uint_as_float((unsigned)(m0 >> 32));
            a.x += nm * v0.x; a.y += nm * v0.y; a.z += nm * v0.z; a.w += nm * v0.w;
            m0 = m1; v0 = v1;
        }
        float nm = __uint_as_float((unsigned)(m0 >> 32));
        a.x += nm * v0.x; a.y += nm * v0.y; a.z += nm * v0.z; a.w += nm * v0.w;
    }
    float4 b = *(const float4*)(b1 + c);
    float4 o;
    o.x = fmaxf(a.x + b.x, 0.f);
    o.y = fmaxf(a.y + b.y, 0.f);
    o.z = fmaxf(a.z + b.z, 0.f);
    o.w = fmaxf(a.w + b.w, 0.f);

    *(float4*)&hidS[w][c] = o;
    __syncwarp();

    const int j  = lane & 15;
    const int k0 = (lane >> 4) << 6;
    float acc = 0.f;
#pragma unroll
    for (int kk = 0; kk < 64; kk += 4) {
        float4 hv = *(float4*)&hidS[w][k0 + kk];
        float4 wv = *(float4*)&W2s[j][k0 + kk];
        acc += hv.x * wv.x + hv.y * wv.y + hv.z * wv.z + hv.w * wv.w;
    }
    acc += __shfl_down_sync(0xffffffffu, acc, 16);
    if (lane < 16) g_h2[(size_t)node * 16 + j] = acc;
}

// ---------------- gather layer 2 + log_softmax (4 lanes per node) ----------

__global__ void __launch_bounds__(256) k_gather2(const float* __restrict__ b2,
                                                 float* __restrict__ out, int n) {
    int g    = blockIdx.x * 256 + threadIdx.x;
    int node = g >> 2, q = g & 3;
    if (node >= n) return;
    int c = q << 2;

    float di  = g_dinv[node];
    float di2 = di * di;
    float4 h  = *(const float4*)(g_h2 + (size_t)node * 16 + c);
    float4 a;
    a.x = di2 * h.x; a.y = di2 * h.y; a.z = di2 * h.z; a.w = di2 * h.w;

    int beg = g_rowptr[node], end = g_rowptr[node + 1];
    if (beg < end) {
        ull m0 = g_emeta[beg];
        float4 v0 = *(const float4*)(g_h2 + (size_t)(unsigned)m0 * 16 + c);
        for (int e = beg + 1; e < end; e++) {
            ull m1 = g_emeta[e];
            float4 v1 = *(const float4*)(g_h2 + (size_t)(unsigned)m1 * 16 + c);
            float nm = __uint_as_float((unsigned)(m0 >> 32));
            a.x += nm * v0.x; a.y += nm * v0.y; a.z += nm * v0.z; a.w += nm * v0.w;
            m0 = m1; v0 = v1;
        }
        float nm = __uint_as_float((unsigned)(m0 >> 32));
        a.x += nm * v0.x; a.y += nm * v0.y; a.z += nm * v0.z; a.w += nm * v0.w;
    }
    float4 b = *(const float4*)(b2 + c);
    a.x += b.x; a.y += b.y; a.z += b.z; a.w += b.w;

    float m4 = fmaxf(fmaxf(a.x, a.y), fmaxf(a.z, a.w));
    m4 = fmaxf(m4, __shfl_xor_sync(0xffffffffu, m4, 1, 4));
    m4 = fmaxf(m4, __shfl_xor_sync(0xffffffffu, m4, 2, 4));
    float s4 = expf(a.x - m4) + expf(a.y - m4) + expf(a.z - m4) + expf(a.w - m4);
    s4 += __shfl_xor_sync(0xffffffffu, s4, 1, 4);
    s4 += __shfl_xor_sync(0xffffffffu, s4, 2, 4);
    float lse = m4 + logf(s4);

    float4 o;
    o.x = a.x - lse; o.y = a.y - lse; o.z = a.z - lse; o.w = a.w - lse;
    *(float4*)(out + (size_t)node * 16 + c) = o;
}

// ---------------------------------------------------------------------------

extern "C" void kernel_launch(void* const* d_in, const int* in_sizes, int n_in,
                              void* d_out, int out_size) {
    const float* x  = (const float*)d_in[0];
    const int*   ei = (const int*)d_in[1];          // int32 (JAX truncation)
    const float* W1 = (const float*)d_in[2];
    const float* b1 = (const float*)d_in[3];
    const float* W2 = (const float*)d_in[4];
    const float* b2 = (const float*)d_in[5];
    float*       out = (float*)d_out;

    const int n = in_sizes[0] / 256;
    const int E = in_sizes[1] / 2;
    const int* src = ei;
    const int* dst = ei + E;
    const int nb = (n + 255) / 256;

    const int T = 256;
    dim3 b(T);

    static cudaStream_t sCsr = nullptr;
    static cudaEvent_t  eFork = nullptr, eJoin = nullptr;
    if (!sCsr) {
        cudaStreamCreateWithFlags(&sCsr, cudaStreamNonBlocking);
        cudaEventCreateWithFlags(&eFork, cudaEventDisableTiming);
        cudaEventCreateWithFlags(&eJoin, cudaEventDisableTiming);
    }

    // fork: CSR build on side stream, GEMM1 on main stream
    cudaEventRecord(eFork, 0);
    cudaStreamWaitEvent(sCsr, eFork, 0);

    k_init     <<<(n + T - 1) / T, b, 0, sCsr>>>(n);
    k_deg_count<<<(E + T - 1) / T, b, 0, sCsr>>>(dst, E);
    k_scan1    <<<nb, b, 0, sCsr>>>(n);

    k_gemm1<<<(n + 127) / 128, b>>>(x, W1, n);

    k_scan2    <<<1, b, 0, sCsr>>>(nb);
    k_scan3    <<<nb, b, 0, sCsr>>>(n);
    k_fill     <<<(E + T - 1) / T, b, 0, sCsr>>>(src, dst, E);
    cudaEventRecord(eJoin, sCsr);

    // join, then the dependent chain
    cudaStreamWaitEvent(0, eJoin, 0);
    k_gather1_gemm2<<<(n + 7) / 8, b>>>(b1, W2, n);
    k_gather2<<<(n * 4 + T - 1) / T, b>>>(b2, out, n);
}

// round 13
// speedup vs baseline: 1.2393x; 1.0351x over previous
#include <cuda_runtime.h>

// ---------------------------------------------------------------------------
// GCN 2-layer forward. CSR aggregation + f32x2 GEMM1 v4 (X-dup, strided cols).
//   h1 = x @ W1                    [N,128]  (FFMA2, conflict-free LDS)
//   hid = relu(A @ h1 + b1)        (registers/smem only)
//   h2 = hid @ W2                  [N,16]   (fused into gather1)
//   out = log_softmax(A @ h2 + b2) [N,16]
// edge_index is int32 (JAX x64-disabled truncates the requested int64).
// CSR build forked onto a side stream, overlapped with GEMM1.
// ---------------------------------------------------------------------------

#define NMAX 50000
#define EMAX 800000
typedef unsigned long long ull;

__device__ int   g_indeg [NMAX];
__device__ int   g_cursor[NMAX];
__device__ int   g_rowptr[NMAX + 1];
__device__ int   g_scan  [NMAX];
__device__ int   g_bsum  [256];
__device__ int   g_boff  [256];
__device__ float g_dinv  [NMAX];
__device__ __align__(16) ull   g_emeta[EMAX];        // hi: norm bits, lo: src
__device__ __align__(16) float g_h1   [NMAX * 128];
__device__ __align__(16) float g_h2   [NMAX * 16];

// ---------------- f32x2 helpers --------------------------------------------

__device__ __forceinline__ void fma2(ull& acc, ull a, ull b) {
    asm("fma.rn.f32x2 %0, %1, %2, %0;" : "+l"(acc) : "l"(a), "l"(b));
}
__device__ __forceinline__ ull dup2(float w) {
    ull d; unsigned u = __float_as_uint(w);
    asm("mov.b64 %0, {%1, %1};" : "=l"(d) : "r"(u));
    return d;
}
__device__ __forceinline__ float f2lo(ull v) { return __uint_as_float((unsigned)v); }
__device__ __forceinline__ float f2hi(ull v) { return __uint_as_float((unsigned)(v >> 32)); }

// ---------------- CSR build ------------------------------------------------

__global__ void k_init(int n) {
    int i = blockIdx.x * blockDim.x + threadIdx.x;
    if (i < n) { g_indeg[i] = 0; g_cursor[i] = 0; }
}

__global__ void k_deg_count(const int* __restrict__ dst, int E) {
    int e = blockIdx.x * blockDim.x + threadIdx.x;
    if (e < E) atomicAdd(&g_indeg[dst[e]], 1);
}

__global__ void k_scan1(int n) {
    __shared__ int wsum[8];
    int t = threadIdx.x, i = blockIdx.x * 256 + t;
    int lane = t & 31, w = t >> 5;
    int x = (i < n) ? g_indeg[i] : 0;
#pragma unroll
    for (int o = 1; o < 32; o <<= 1) {
        int y = __shfl_up_sync(0xffffffffu, x, o);
        if (lane >= o) x += y;
    }
    if (lane == 31) wsum[w] = x;
    __syncthreads();
    if (w == 0) {
        int s = (lane < 8) ? wsum[lane] : 0;
#pragma unroll
        for (int o = 1; o < 8; o <<= 1) {
            int y = __shfl_up_sync(0xffffffffu, s, o);
            if (lane >= o) s += y;
        }
        if (lane < 8) wsum[lane] = s;
    }
    __syncthreads();
    if (w > 0) x += wsum[w - 1];
    if (i < n) g_scan[i] = x;
    if (t == 255) g_bsum[blockIdx.x] = x;
}

__global__ void k_scan2(int nb) {
    __shared__ int wsum[8];
    int t = threadIdx.x;
    int lane = t & 31, w = t >> 5;
    int v = (t < nb) ? g_bsum[t] : 0;
    int x = v;
#pragma unroll
    for (int o = 1; o < 32; o <<= 1) {
        int y = __shfl_up_sync(0xffffffffu, x, o);
        if (lane >= o) x += y;
    }
    if (lane == 31) wsum[w] = x;
    __syncthreads();
    if (w == 0) {
        int s = (lane < 8) ? wsum[lane] : 0;
#pragma unroll
        for (int o = 1; o < 8; o <<= 1) {
            int y = __shfl_up_sync(0xffffffffu, s, o);
            if (lane >= o) s += y;
        }
        if (lane < 8) wsum[lane] = s;
    }
    __syncthreads();
    if (w > 0) x += wsum[w - 1];
    g_boff[t] = x - v;   // exclusive
}

__global__ void k_scan3(int n) {     // rowptr + dinv
    int i = blockIdx.x * blockDim.x + threadIdx.x;
    if (i >= n) return;
    int deg = g_indeg[i];
    int off = g_boff[i >> 8];
    g_rowptr[i] = g_scan[i] - deg + off;
    if (i == n - 1) g_rowptr[n] = g_scan[i] + off;
    g_dinv[i] = rsqrtf((float)(deg + 1));
}

__global__ void k_fill(const int* __restrict__ src, const int* __restrict__ dst, int E) {
    int e = blockIdx.x * blockDim.x + threadIdx.x;
    if (e >= E) return;
    int s = src[e], d = dst[e];
    int pos = g_rowptr[d] + atomicAdd(&g_cursor[d], 1);
    float nm = g_dinv[s] * g_dinv[d];
    g_emeta[pos] = ((ull)__float_as_uint(nm) << 32) | (unsigned)s;
}

// ---------------- GEMM1 v4: h1 = x @ W1  (K=256, 128 cols) -----------------
// 128x128 tile, 256 threads, 8 rows x 8 cols per thread, K-chunks of 16.
// X stored DUPLICATED (x,x) per row (dup paid at staging; inner loads are
// 2-address broadcasts = 1 phase). W natural; thread cg owns col-pairs
// {2cg, 2cg+32, 2cg+64, 2cg+96} so each W LDS.64 puts 16 lanes at 8B
// stride across all 32 banks = 1 phase (lanes 16-31 broadcast-merge).
// Per warp-kk: 12 crossbar phases per 32 FFMA2 -> FFMA2-issue-bound.

__global__ void __launch_bounds__(256, 2) k_gemm1(const float* __restrict__ X,
                                                  const float* __restrict__ W,
                                                  int n) {
    __shared__ ull   XsD[16][130];   // [kk][row] = (x,x); pad to de-conflict STS
    __shared__ float Wn [16][128];   // [kk][col] natural
    const int tid = threadIdx.x;
    const int cg  = tid & 15;        // col-pairs 2cg + {0,32,64,96}
    const int rg  = tid >> 4;        // rows 8*rg .. +7
    const int row0 = blockIdx.x * 128;
    const int rbase = rg << 3;
    const int cbase = cg << 1;

    ull acc[8][4];
#pragma unroll
    for (int r = 0; r < 8; r++)
#pragma unroll
        for (int c = 0; c < 4; c++) acc[r][c] = 0ull;

    for (int ch = 0; ch < 16; ch++) {
        const int k0 = ch << 4;
        // ---- stage X: 128 rows x 16 k, dup-packed ----
#pragma unroll
        for (int i = tid; i < 512; i += 256) {
            int r = i >> 2, f4 = i & 3;
            int gr = row0 + r;
            float4 v = make_float4(0.f, 0.f, 0.f, 0.f);
            if (gr < n) v = *(const float4*)(X + (size_t)gr * 256 + k0 + (f4 << 2));
            XsD[(f4 << 2) + 0][r] = dup2(v.x);
            XsD[(f4 << 2) + 1][r] = dup2(v.y);
            XsD[(f4 << 2) + 2][r] = dup2(v.z);
            XsD[(f4 << 2) + 3][r] = dup2(v.w);
        }
        // ---- stage W natural: 16 k x 128 cols ----
#pragma unroll
        for (int i = tid; i < 512; i += 256) {
            int kk = i >> 5, c0 = (i & 31) << 2;
            *(float4*)&Wn[kk][c0] = *(const float4*)(W + (size_t)(k0 + kk) * 128 + c0);
        }
        __syncthreads();

#pragma unroll
        for (int kk = 0; kk < 16; kk++) {
            // W: 4 conflict-free LDS.64 (8B stride spans all banks)
            ull w0 = *(const ull*)&Wn[kk][cbase];
            ull w1 = *(const ull*)&Wn[kk][cbase + 32];
            ull w2 = *(const ull*)&Wn[kk][cbase + 64];
            ull w3 = *(const ull*)&Wn[kk][cbase + 96];
            // X: 8 broadcast LDS.64 (2 addresses per warp)
#pragma unroll
            for (int j = 0; j < 4; j++) {
                ull xa = XsD[kk][rbase + 2 * j];
                ull xb = XsD[kk][rbase + 2 * j + 1];
                fma2(acc[2 * j][0], xa, w0);
                fma2(acc[2 * j][1], xa, w1);
                fma2(acc[2 * j][2], xa, w2);
                fma2(acc[2 * j][3], xa, w3);
                fma2(acc[2 * j + 1][0], xb, w0);
                fma2(acc[2 * j + 1][1], xb, w1);
                fma2(acc[2 * j + 1][2], xb, w2);
                fma2(acc[2 * j + 1][3], xb, w3);
            }
        }
        __syncthreads();
    }

    // ---- epilogue: acc[r][p] = cols (2cg+32p, 2cg+32p+1) of row rbase+r ----
#pragma unroll
    for (int r = 0; r < 8; r++) {
        int gr = row0 + rbase + r;
        if (gr < n) {
            float* dst = g_h1 + (size_t)gr * 128 + cbase;
#pragma unroll
            for (int p = 0; p < 4; p++)
                *(ull*)(dst + 32 * p) = acc[r][p];
        }
    }
}

// ---------------- fused gather1 + GEMM2 (warp per node) --------------------

__global__ void __launch_bounds__(256) k_gather1_gemm2(const float* __restrict__ b1,
                                                       const float* __restrict__ W2,
                                                       int n) {
    __shared__ float W2s[16][132];        // W2s[j][k] = W2[k][j] (transposed, padded)
    __shared__ float hidS[8][128];        // per-warp hid row
    const int tid  = threadIdx.x;
    const int w    = tid >> 5;
    const int lane = tid & 31;

#pragma unroll
    for (int i = tid; i < 2048; i += 256) {
        int k = i >> 4, j = i & 15;
        W2s[j][k] = W2[k * 16 + j];
    }
    __syncthreads();

    int node = blockIdx.x * 8 + w;
    if (node >= n) return;
    int c = lane << 2;

    float di  = g_dinv[node];
    float di2 = di * di;
    float4 h  = *(const float4*)(g_h1 + (size_t)node * 128 + c);
    float4 a;
    a.x = di2 * h.x; a.y = di2 * h.y; a.z = di2 * h.z; a.w = di2 * h.w;

    int beg = g_rowptr[node], end = g_rowptr[node + 1];
    if (beg < end) {
        ull m0 = g_emeta[beg];
        float4 v0 = *(const float4*)(g_h1 + (size_t)(unsigned)m0 * 128 + c);
        for (int e = beg + 1; e < end; e++) {
            ull m1 = g_emeta[e];
            float4 v1 = *(const float4*)(g_h1 + (size_t)(unsigned)m1 * 128 + c);
            float nm = __uint_as_float((unsigned)(m0 >> 32));
            a.x += nm * v0.x; a.y += nm * v0.y; a.z += nm * v0.z; a.w += nm * v0.w;
            m0 = m1; v0 = v1;
        }
        float nm = __uint_as_float((unsigned)(m0 >> 32));
        a.x += nm * v0.x; a.y += nm * v0.y; a.z += nm * v0.z; a.w += nm * v0.w;
    }
    float4 b = *(const float4*)(b1 + c);
    float4 o;
    o.x = fmaxf(a.x + b.x, 0.f);
    o.y = fmaxf(a.y + b.y, 0.f);
    o.z = fmaxf(a.z + b.z, 0.f);
    o.w = fmaxf(a.w + b.w, 0.f);

    *(float4*)&hidS[w][c] = o;
    __syncwarp();

    const int j  = lane & 15;
    const int k0 = (lane >> 4) << 6;
    float acc = 0.f;
#pragma unroll
    for (int kk = 0; kk < 64; kk += 4) {
        float4 hv = *(float4*)&hidS[w][k0 + kk];
        float4 wv = *(float4*)&W2s[j][k0 + kk];
        acc += hv.x * wv.x + hv.y * wv.y + hv.z * wv.z + hv.w * wv.w;
    }
    acc += __shfl_down_sync(0xffffffffu, acc, 16);
    if (lane < 16) g_h2[(size_t)node * 16 + j] = acc;
}

// ---------------- gather layer 2 + log_softmax (4 lanes per node) ----------

__global__ void __launch_bounds__(256) k_gather2(const float* __restrict__ b2,
                                                 float* __restrict__ out, int n) {
    int g    = blockIdx.x * 256 + threadIdx.x;
    int node = g >> 2, q = g & 3;
    if (node >= n) return;
    int c = q << 2;

    float di  = g_dinv[node];
    float di2 = di * di;
    float4 h  = *(const float4*)(g_h2 + (size_t)node * 16 + c);
    float4 a;
    a.x = di2 * h.x; a.y = di2 * h.y; a.z = di2 * h.z; a.w = di2 * h.w;

    int beg = g_rowptr[node], end = g_rowptr[node + 1];
    if (beg < end) {
        ull m0 = g_emeta[beg];
        float4 v0 = *(const float4*)(g_h2 + (size_t)(unsigned)m0 * 16 + c);
        for (int e = beg + 1; e < end; e++) {
            ull m1 = g_emeta[e];
            float4 v1 = *(const float4*)(g_h2 + (size_t)(unsigned)m1 * 16 + c);
            float nm = __uint_as_float((unsigned)(m0 >> 32));
            a.x += nm * v0.x; a.y += nm * v0.y; a.z += nm * v0.z; a.w += nm * v0.w;
            m0 = m1; v0 = v1;
        }
        float nm = __uint_as_float((unsigned)(m0 >> 32));
        a.x += nm * v0.x; a.y += nm * v0.y; a.z += nm * v0.z; a.w += nm * v0.w;
    }
    float4 b = *(const float4*)(b2 + c);
    a.x += b.x; a.y += b.y; a.z += b.z; a.w += b.w;

    float m4 = fmaxf(fmaxf(a.x, a.y), fmaxf(a.z, a.w));
    m4 = fmaxf(m4, __shfl_xor_sync(0xffffffffu, m4, 1, 4));
    m4 = fmaxf(m4, __shfl_xor_sync(0xffffffffu, m4, 2, 4));
    float s4 = expf(a.x - m4) + expf(a.y - m4) + expf(a.z - m4) + expf(a.w - m4);
    s4 += __shfl_xor_sync(0xffffffffu, s4, 1, 4);
    s4 += __shfl_xor_sync(0xffffffffu, s4, 2, 4);
    float lse = m4 + logf(s4);

    float4 o;
    o.x = a.x - lse; o.y = a.y - lse; o.z = a.z - lse; o.w = a.w - lse;
    *(float4*)(out + (size_t)node * 16 + c) = o;
}

// ---------------------------------------------------------------------------

extern "C" void kernel_launch(void* const* d_in, const int* in_sizes, int n_in,
                              void* d_out, int out_size) {
    const float* x  = (const float*)d_in[0];
    const int*   ei = (const int*)d_in[1];          // int32 (JAX truncation)
    const float* W1 = (const float*)d_in[2];
    const float* b1 = (const float*)d_in[3];
    const float* W2 = (const float*)d_in[4];
    const float* b2 = (const float*)d_in[5];
    float*       out = (float*)d_out;

    const int n = in_sizes[0] / 256;
    const int E = in_sizes[1] / 2;
    const int* src = ei;
    const int* dst = ei + E;
    const int nb = (n + 255) / 256;

    const int T = 256;
    dim3 b(T);

    static cudaStream_t sCsr = nullptr;
    static cudaEvent_t  eFork = nullptr, eJoin = nullptr;
    if (!sCsr) {
        cudaStreamCreateWithFlags(&sCsr, cudaStreamNonBlocking);
        cudaEventCreateWithFlags(&eFork, cudaEventDisableTiming);
        cudaEventCreateWithFlags(&eJoin, cudaEventDisableTiming);
    }

    // fork: CSR build on side stream, GEMM1 on main stream
    cudaEventRecord(eFork, 0);
    cudaStreamWaitEvent(sCsr, eFork, 0);

    k_init     <<<(n + T - 1) / T, b, 0, sCsr>>>(n);
    k_deg_count<<<(E + T - 1) / T, b, 0, sCsr>>>(dst, E);
    k_scan1    <<<nb, b, 0, sCsr>>>(n);

    k_gemm1<<<(n + 127) / 128, b>>>(x, W1, n);

    k_scan2    <<<1, b, 0, sCsr>>>(nb);
    k_scan3    <<<nb, b, 0, sCsr>>>(n);
    k_fill     <<<(E + T - 1) / T, b, 0, sCsr>>>(src, dst, E);
    cudaEventRecord(eJoin, sCsr);

    // join, then the dependent chain
    cudaStreamWaitEvent(0, eJoin, 0);
    k_gather1_gemm2<<<(n + 7) / 8, b>>>(b1, W2, n);
    k_gather2<<<(n * 4 + T - 1) / T, b>>>(b2, out, n);
}

// round 15
// speedup vs baseline: 1.6916x; 1.3650x over previous
#include <cuda_runtime.h>
#include <cuda_bf16.h>

// ---------------------------------------------------------------------------
// GCN 2-layer forward. CSR aggregation + mma.sync bf16-split GEMM1.
//   h1 = x @ W1                    [N,128]  (HMMA m16n8k16, 3-way bf16 split)
//   hid = relu(A @ h1 + b1)        (registers/smem only)
//   h2 = hid @ W2                  [N,16]   (fused into gather1)
//   out = log_softmax(A @ h2 + b2) [N,16]
// edge_index is int32 (JAX x64-disabled truncates the requested int64).
// CSR build forked onto a side stream, overlapped with GEMM1.
// NOTE: mma.sync/ldmatrix are baseline sm_80+ PTX (compile for compute_103
// is fine); only tcgen05-class ops need the 'a' target.
// ---------------------------------------------------------------------------

#define NMAX 50000
#define EMAX 800000
typedef unsigned long long ull;

__device__ int   g_indeg [NMAX];
__device__ int   g_cursor[NMAX];
__device__ int   g_rowptr[NMAX + 1];
__device__ int   g_scan  [NMAX];
__device__ int   g_bsum  [256];
__device__ int   g_boff  [256];
__device__ float g_dinv  [NMAX];
__device__ __align__(16) ull   g_emeta[EMAX];        // hi: norm bits, lo: src
__device__ __align__(16) float g_h1   [NMAX * 128];
__device__ __align__(16) float g_h2   [NMAX * 16];

// ---------------- helpers ---------------------------------------------------

__device__ __forceinline__ ull pack2f(float lo, float hi) {
    ull d;
    asm("mov.b64 %0, {%1, %2};" : "=l"(d) : "r"(__float_as_uint(lo)), "r"(__float_as_uint(hi)));
    return d;
}
__device__ __forceinline__ void ldm_x4(unsigned& r0, unsigned& r1, unsigned& r2, unsigned& r3,
                                       unsigned addr) {
    asm volatile("ldmatrix.sync.aligned.m8n8.x4.shared.b16 {%0,%1,%2,%3}, [%4];"
                 : "=r"(r0), "=r"(r1), "=r"(r2), "=r"(r3) : "r"(addr));
}
__device__ __forceinline__ void ldm_x4t(unsigned& r0, unsigned& r1, unsigned& r2, unsigned& r3,
                                        unsigned addr) {
    asm volatile("ldmatrix.sync.aligned.m8n8.x4.trans.shared.b16 {%0,%1,%2,%3}, [%4];"
                 : "=r"(r0), "=r"(r1), "=r"(r2), "=r"(r3) : "r"(addr));
}
__device__ __forceinline__ void mma_bf16(float* c, const unsigned* a, unsigned b0, unsigned b1) {
    asm volatile("mma.sync.aligned.m16n8k16.row.col.f32.bf16.bf16.f32 "
                 "{%0,%1,%2,%3}, {%4,%5,%6,%7}, {%8,%9}, {%0,%1,%2,%3};"
                 : "+f"(c[0]), "+f"(c[1]), "+f"(c[2]), "+f"(c[3])
                 : "r"(a[0]), "r"(a[1]), "r"(a[2]), "r"(a[3]), "r"(b0), "r"(b1));
}

// ---------------- CSR build ------------------------------------------------

__global__ void k_init(int n) {
    int i = blockIdx.x * blockDim.x + threadIdx.x;
    if (i < n) { g_indeg[i] = 0; g_cursor[i] = 0; }
}

__global__ void k_deg_count(const int* __restrict__ dst, int E) {
    int e = blockIdx.x * blockDim.x + threadIdx.x;
    if (e < E) atomicAdd(&g_indeg[dst[e]], 1);
}

__global__ void k_scan1(int n) {
    __shared__ int wsum[8];
    int t = threadIdx.x, i = blockIdx.x * 256 + t;
    int lane = t & 31, w = t >> 5;
    int x = (i < n) ? g_indeg[i] : 0;
#pragma unroll
    for (int o = 1; o < 32; o <<= 1) {
        int y = __shfl_up_sync(0xffffffffu, x, o);
        if (lane >= o) x += y;
    }
    if (lane == 31) wsum[w] = x;
    __syncthreads();
    if (w == 0) {
        int s = (lane < 8) ? wsum[lane] : 0;
#pragma unroll
        for (int o = 1; o < 8; o <<= 1) {
            int y = __shfl_up_sync(0xffffffffu, s, o);
            if (lane >= o) s += y;
        }
        if (lane < 8) wsum[lane] = s;
    }
    __syncthreads();
    if (w > 0) x += wsum[w - 1];
    if (i < n) g_scan[i] = x;
    if (t == 255) g_bsum[blockIdx.x] = x;
}

__global__ void k_scan2(int nb) {
    __shared__ int wsum[8];
    int t = threadIdx.x;
    int lane = t & 31, w = t >> 5;
    int v = (t < nb) ? g_bsum[t] : 0;
    int x = v;
#pragma unroll
    for (int o = 1; o < 32; o <<= 1) {
        int y = __shfl_up_sync(0xffffffffu, x, o);
        if (lane >= o) x += y;
    }
    if (lane == 31) wsum[w] = x;
    __syncthreads();
    if (w == 0) {
        int s = (lane < 8) ? wsum[lane] : 0;
#pragma unroll
        for (int o = 1; o < 8; o <<= 1) {
            int y = __shfl_up_sync(0xffffffffu, s, o);
            if (lane >= o) s += y;
        }
        if (lane < 8) wsum[lane] = s;
    }
    __syncthreads();
    if (w > 0) x += wsum[w - 1];
    g_boff[t] = x - v;   // exclusive
}

__global__ void k_scan3(int n) {     // rowptr + dinv
    int i = blockIdx.x * blockDim.x + threadIdx.x;
    if (i >= n) return;
    int deg = g_indeg[i];
    int off = g_boff[i >> 8];
    g_rowptr[i] = g_scan[i] - deg + off;
    if (i == n - 1) g_rowptr[n] = g_scan[i] + off;
    g_dinv[i] = rsqrtf((float)(deg + 1));
}

__global__ void k_fill(const int* __restrict__ src, const int* __restrict__ dst, int E) {
    int e = blockIdx.x * blockDim.x + threadIdx.x;
    if (e >= E) return;
    int s = src[e], d = dst[e];
    int pos = g_rowptr[d] + atomicAdd(&g_cursor[d], 1);
    float nm = g_dinv[s] * g_dinv[d];
    g_emeta[pos] = ((ull)__float_as_uint(nm) << 32) | (unsigned)s;
}

// ---------------- GEMM1 via mma.sync: h1 = x @ W1 --------------------------
// 128x128 tile, 256 thr (8 warps: 4 m-warps x 2 n-warps), K-chunks of 32.
// x = hi+lo bf16 split (A), W = hi+lo bf16 split (B); D += AhBh + AhBl + AlBh.
// A smem [128][40] bf16 (pitch 20 words: 8-row ldmatrix phases conflict-free).
// B smem [32][136] bf16, k-major; fragments via ldmatrix.x4.trans
//   (pitch 68 words = 4 mod 32: phases conflict-free).

#define A_PITCH 40
#define B_PITCH 136

__global__ void __launch_bounds__(256, 2) k_gemm1(const float* __restrict__ X,
                                                  const float* __restrict__ W,
                                                  int n) {
    __shared__ __align__(16) __nv_bfloat16 Ah[128][A_PITCH];
    __shared__ __align__(16) __nv_bfloat16 Al[128][A_PITCH];
    __shared__ __align__(16) __nv_bfloat16 Bh[32][B_PITCH];
    __shared__ __align__(16) __nv_bfloat16 Bl[32][B_PITCH];

    const int tid  = threadIdx.x;
    const int wid  = tid >> 5;
    const int lane = tid & 31;
    const int wm   = wid & 3;          // m-warp: rows wm*32..+31
    const int wn   = wid >> 2;         // n-warp: cols wn*64..+63
    const int row0 = blockIdx.x * 128;

    float acc[2][8][4];                // [mtile][n8tile][frag]
#pragma unroll
    for (int mt = 0; mt < 2; mt++)
#pragma unroll
        for (int nt = 0; nt < 8; nt++)
#pragma unroll
            for (int q = 0; q < 4; q++) acc[mt][nt][q] = 0.f;

    for (int ch = 0; ch < 8; ch++) {
        const int k0 = ch << 5;
        // ---- stage A (X): 128 rows x 32 k, bf16 hi/lo ----
#pragma unroll
        for (int i = tid; i < 1024; i += 256) {
            int r = i >> 3, f4 = i & 7;
            int gr = row0 + r;
            float4 v = make_float4(0.f, 0.f, 0.f, 0.f);
            if (gr < n) v = *(const float4*)(X + (size_t)gr * 256 + k0 + (f4 << 2));
            float xs[4] = {v.x, v.y, v.z, v.w};
            unsigned hw0 = 0, hw1 = 0, lw0 = 0, lw1 = 0;
            {
                __nv_bfloat16 h0 = __float2bfloat16(xs[0]);
                __nv_bfloat16 h1b = __float2bfloat16(xs[1]);
                __nv_bfloat16 l0 = __float2bfloat16(xs[0] - __bfloat162float(h0));
                __nv_bfloat16 l1 = __float2bfloat16(xs[1] - __bfloat162float(h1b));
                hw0 = (unsigned)__bfloat16_as_ushort(h0) | ((unsigned)__bfloat16_as_ushort(h1b) << 16);
                lw0 = (unsigned)__bfloat16_as_ushort(l0) | ((unsigned)__bfloat16_as_ushort(l1) << 16);
            }
            {
                __nv_bfloat16 h0 = __float2bfloat16(xs[2]);
                __nv_bfloat16 h1b = __float2bfloat16(xs[3]);
                __nv_bfloat16 l0 = __float2bfloat16(xs[2] - __bfloat162float(h0));
                __nv_bfloat16 l1 = __float2bfloat16(xs[3] - __bfloat162float(h1b));
                hw1 = (unsigned)__bfloat16_as_ushort(h0) | ((unsigned)__bfloat16_as_ushort(h1b) << 16);
                lw1 = (unsigned)__bfloat16_as_ushort(l0) | ((unsigned)__bfloat16_as_ushort(l1) << 16);
            }
            *(ull*)&Ah[r][f4 << 2] = ((ull)hw1 << 32) | hw0;
            *(ull*)&Al[r][f4 << 2] = ((ull)lw1 << 32) | lw0;
        }
        // ---- stage B (W): 32 k x 128 n, k-major, bf16 hi/lo ----
#pragma unroll
        for (int i = tid; i < 1024; i += 256) {
            int kk = i >> 5, n0 = (i & 31) << 2;
            float4 v = *(const float4*)(W + (size_t)(k0 + kk) * 128 + n0);
            float xs[4] = {v.x, v.y, v.z, v.w};
            unsigned hw0, hw1, lw0, lw1;
            {
                __nv_bfloat16 h0 = __float2bfloat16(xs[0]);
                __nv_bfloat16 h1b = __float2bfloat16(xs[1]);
                __nv_bfloat16 l0 = __float2bfloat16(xs[0] - __bfloat162float(h0));
                __nv_bfloat16 l1 = __float2bfloat16(xs[1] - __bfloat162float(h1b));
                hw0 = (unsigned)__bfloat16_as_ushort(h0) | ((unsigned)__bfloat16_as_ushort(h1b) << 16);
                lw0 = (unsigned)__bfloat16_as_ushort(l0) | ((unsigned)__bfloat16_as_ushort(l1) << 16);
            }
            {
                __nv_bfloat16 h0 = __float2bfloat16(xs[2]);
                __nv_bfloat16 h1b = __float2bfloat16(xs[3]);
                __nv_bfloat16 l0 = __float2bfloat16(xs[2] - __bfloat162float(h0));
                __nv_bfloat16 l1 = __float2bfloat16(xs[3] - __bfloat162float(h1b));
                hw1 = (unsigned)__bfloat16_as_ushort(h0) | ((unsigned)__bfloat16_as_ushort(h1b) << 16);
                lw1 = (unsigned)__bfloat16_as_ushort(l0) | ((unsigned)__bfloat16_as_ushort(l1) << 16);
            }
            *(ull*)&Bh[kk][n0] = ((ull)hw1 << 32) | hw0;
            *(ull*)&Bl[kk][n0] = ((ull)lw1 << 32) | lw0;
        }
        __syncthreads();

#pragma unroll
        for (int ks = 0; ks < 32; ks += 16) {
            // A fragments: m-tiles {0,16}+wm*32, k16 at ks, hi+lo
            unsigned aH[2][4], aL[2][4];
#pragma unroll
            for (int mt = 0; mt < 2; mt++) {
                int ar = wm * 32 + mt * 16 + (lane & 15);
                int ac = ks + ((lane >> 4) << 3);
                unsigned addrH = (unsigned)__cvta_generic_to_shared(&Ah[ar][ac]);
                unsigned addrL = (unsigned)__cvta_generic_to_shared(&Al[ar][ac]);
                ldm_x4(aH[mt][0], aH[mt][1], aH[mt][2], aH[mt][3], addrH);
                ldm_x4(aL[mt][0], aL[mt][1], aL[mt][2], aL[mt][3], addrL);
            }
#pragma unroll
            for (int ng = 0; ng < 4; ng++) {
                int nb0 = wn * 64 + ng * 16;
                int br = ks + (lane & 15);
                int bc = nb0 + ((lane >> 4) << 3);
                unsigned addrH = (unsigned)__cvta_generic_to_shared(&Bh[br][bc]);
                unsigned addrL = (unsigned)__cvta_generic_to_shared(&Bl[br][bc]);
                unsigned bh[4], bl[4];
                ldm_x4t(bh[0], bh[1], bh[2], bh[3], addrH);
                ldm_x4t(bl[0], bl[1], bl[2], bl[3], addrL);
#pragma unroll
                for (int mt = 0; mt < 2; mt++) {
#pragma unroll
                    for (int nt = 0; nt < 2; nt++) {
                        float* c = acc[mt][ng * 2 + nt];
                        mma_bf16(c, aH[mt], bh[nt * 2], bh[nt * 2 + 1]);   // hi*hi
                        mma_bf16(c, aH[mt], bl[nt * 2], bl[nt * 2 + 1]);   // hi*lo
                        mma_bf16(c, aL[mt], bh[nt * 2], bh[nt * 2 + 1]);   // lo*hi
                    }
                }
            }
        }
        __syncthreads();
    }

    // ---- epilogue: c frag (m16n8): c0,c1 -> row lane/4, cols (lane%4)*2+{0,1};
    //      c2,c3 -> row +8 ----
#pragma unroll
    for (int mt = 0; mt < 2; mt++) {
#pragma unroll
        for (int nt = 0; nt < 8; nt++) {
            int col = wn * 64 + nt * 8 + ((lane & 3) << 1);
            int r0  = row0 + wm * 32 + mt * 16 + (lane >> 2);
            if (r0 < n)
                *(ull*)(g_h1 + (size_t)r0 * 128 + col) = pack2f(acc[mt][nt][0], acc[mt][nt][1]);
            if (r0 + 8 < n)
                *(ull*)(g_h1 + (size_t)(r0 + 8) * 128 + col) = pack2f(acc[mt][nt][2], acc[mt][nt][3]);
        }
    }
}

// ---------------- fused gather1 + GEMM2 (warp per node) --------------------

__global__ void __launch_bounds__(256) k_gather1_gemm2(const float* __restrict__ b1,
                                                       const float* __restrict__ W2,
                                                       int n) {
    __shared__ float W2s[16][132];        // W2s[j][k] = W2[k][j] (transposed, padded)
    __shared__ float hidS[8][128];        // per-warp hid row
    const int tid  = threadIdx.x;
    const int w    = tid >> 5;
    const int lane = tid & 31;

#pragma unroll
    for (int i = tid; i < 2048; i += 256) {
        int k = i >> 4, j = i & 15;
        W2s[j][k] = W2[k * 16 + j];
    }
    __syncthreads();

    int node = blockIdx.x * 8 + w;
    if (node >= n) return;
    int c = lane << 2;

    float di  = g_dinv[node];
    float di2 = di * di;
    float4 h  = *(const float4*)(g_h1 + (size_t)node * 128 + c);
    float4 a;
    a.x = di2 * h.x; a.y = di2 * h.y; a.z = di2 * h.z; a.w = di2 * h.w;

    int beg = g_rowptr[node], end = g_rowptr[node + 1];
    if (beg < end) {
        ull m0 = g_emeta[beg];
        float4 v0 = *(const float4*)(g_h1 + (size_t)(unsigned)m0 * 128 + c);
        for (int e = beg + 1; e < end; e++) {
            ull m1 = g_emeta[e];
            float4 v1 = *(const float4*)(g_h1 + (size_t)(unsigned)m1 * 128 + c);
            float nm = __uint_as_float((unsigned)(m0 >> 32));
            a.x += nm * v0.x; a.y += nm * v0.y; a.z += nm * v0.z; a.w += nm * v0.w;
            m0 = m1; v0 = v1;
        }
        float nm = __uint_as_float((unsigned)(m0 >> 32));
        a.x += nm * v0.x; a.y += nm * v0.y; a.z += nm * v0.z; a.w += nm * v0.w;
    }
    float4 b = *(const float4*)(b1 + c);
    float4 o;
    o.x = fmaxf(a.x + b.x, 0.f);
    o.y = fmaxf(a.y + b.y, 0.f);
    o.z = fmaxf(a.z + b.z, 0.f);
    o.w = fmaxf(a.w + b.w, 0.f);

    *(float4*)&hidS[w][c] = o;
    __syncwarp();

    const int j  = lane & 15;
    const int k0 = (lane >> 4) << 6;
    float acc = 0.f;
#pragma unroll
    for (int kk = 0; kk < 64; kk += 4) {
        float4 hv = *(float4*)&hidS[w][k0 + kk];
        float4 wv = *(float4*)&W2s[j][k0 + kk];
        acc += hv.x * wv.x + hv.y * wv.y + hv.z * wv.z + hv.w * wv.w;
    }
    acc += __shfl_down_sync(0xffffffffu, acc, 16);
    if (lane < 16) g_h2[(size_t)node * 16 + j] = acc;
}

// ---------------- gather layer 2 + log_softmax (4 lanes per node) ----------

__global__ void __launch_bounds__(256) k_gather2(const float* __restrict__ b2,
                                                 float* __restrict__ out, int n) {
    int g    = blockIdx.x * 256 + threadIdx.x;
    int node = g >> 2, q = g & 3;
    if (node >= n) return;
    int c = q << 2;

    float di  = g_dinv[node];
    float di2 = di * di;
    float4 h  = *(const float4*)(g_h2 + (size_t)node * 16 + c);
    float4 a;
    a.x = di2 * h.x; a.y = di2 * h.y; a.z = di2 * h.z; a.w = di2 * h.w;

    int beg = g_rowptr[node], end = g_rowptr[node + 1];
    if (beg < end) {
        ull m0 = g_emeta[beg];
        float4 v0 = *(const float4*)(g_h2 + (size_t)(unsigned)m0 * 16 + c);
        for (int e = beg + 1; e < end; e++) {
            ull m1 = g_emeta[e];
            float4 v1 = *(const float4*)(g_h2 + (size_t)(unsigned)m1 * 16 + c);
            float nm = __uint_as_float((unsigned)(m0 >> 32));
            a.x += nm * v0.x; a.y += nm * v0.y; a.z += nm * v0.z; a.w += nm * v0.w;
            m0 = m1; v0 = v1;
        }
        float nm = __uint_as_float((unsigned)(m0 >> 32));
        a.x += nm * v0.x; a.y += nm * v0.y; a.z += nm * v0.z; a.w += nm * v0.w;
    }
    float4 b = *(const float4*)(b2 + c);
    a.x += b.x; a.y += b.y; a.z += b.z; a.w += b.w;

    float m4 = fmaxf(fmaxf(a.x, a.y), fmaxf(a.z, a.w));
    m4 = fmaxf(m4, __shfl_xor_sync(0xffffffffu, m4, 1, 4));
    m4 = fmaxf(m4, __shfl_xor_sync(0xffffffffu, m4, 2, 4));
    float s4 = expf(a.x - m4) + expf(a.y - m4) + expf(a.z - m4) + expf(a.w - m4);
    s4 += __shfl_xor_sync(0xffffffffu, s4, 1, 4);
    s4 += __shfl_xor_sync(0xffffffffu, s4, 2, 4);
    float lse = m4 + logf(s4);

    float4 o;
    o.x = a.x - lse; o.y = a.y - lse; o.z = a.z - lse; o.w = a.w - lse;
    *(float4*)(out + (size_t)node * 16 + c) = o;
}

// ---------------------------------------------------------------------------

extern "C" void kernel_launch(void* const* d_in, const int* in_sizes, int n_in,
                              void* d_out, int out_size) {
    const float* x  = (const float*)d_in[0];
    const int*   ei = (const int*)d_in[1];          // int32 (JAX truncation)
    const float* W1 = (const float*)d_in[2];
    const float* b1 = (const float*)d_in[3];
    const float* W2 = (const float*)d_in[4];
    const float* b2 = (const float*)d_in[5];
    float*       out = (float*)d_out;

    const int n = in_sizes[0] / 256;
    const int E = in_sizes[1] / 2;
    const int* src = ei;
    const int* dst = ei + E;
    const int nb = (n + 255) / 256;

    const int T = 256;
    dim3 b(T);

    static cudaStream_t sCsr = nullptr;
    static cudaEvent_t  eFork = nullptr, eJoin = nullptr;
    if (!sCsr) {
        cudaStreamCreateWithFlags(&sCsr, cudaStreamNonBlocking);
        cudaEventCreateWithFlags(&eFork, cudaEventDisableTiming);
        cudaEventCreateWithFlags(&eJoin, cudaEventDisableTiming);
    }

    // fork: CSR build on side stream, GEMM1 on main stream
    cudaEventRecord(eFork, 0);
    cudaStreamWaitEvent(sCsr, eFork, 0);

    k_init     <<<(n + T - 1) / T, b, 0, sCsr>>>(n);
    k_deg_count<<<(E + T - 1) / T, b, 0, sCsr>>>(dst, E);
    k_scan1    <<<nb, b, 0, sCsr>>>(n);

    k_gemm1<<<(n + 127) / 128, b>>>(x, W1, n);

    k_scan2    <<<1, b, 0, sCsr>>>(nb);
    k_scan3    <<<nb, b, 0, sCsr>>>(n);
    k_fill     <<<(E + T - 1) / T, b, 0, sCsr>>>(src, dst, E);
    cudaEventRecord(eJoin, sCsr);

    // join, then the dependent chain
    cudaStreamWaitEvent(0, eJoin, 0);
    k_gather1_gemm2<<<(n + 7) / 8, b>>>(b1, W2, n);
    k_gather2<<<(n * 4 + T - 1) / T, b>>>(b2, out, n);
}